// round 17
// baseline (speedup 1.0000x reference)
#include <cuda_runtime.h>
#include <cstdint>
#include <cstddef>

// Monarch embedding, analytically folded:
//   out[tok][kr*32+o] = (kr&1 == s) ? L[v*16 + kr/2] * R[(kr*32 + c)*32 + o] : 0
//   v = x[tok], k = v/786, s = k>>5, c = k&31.
//
// R17 = R11 (measured best: 12.83us ncu) + zero-stores-first reorder.
// Converged model: the LTS *store* path (~half the 6300 B/cyc load cap)
// bounds the mandatory 64MiB output stream at ~12.2us; R11 is ~95% of that
// floor. This round only pulls the dependency-free zero stores ahead of the
// active-token load-consume chain so the store queue is fed during the
// L-gather shadow (zero stores depend on x->idiv only: one L2 hop, not two).
//
// Map: 256 thr, th = tid>>7 (token of pair), slot = tid&127,
//   u = slot>>5, l = slot&31, p = u&1 (warp parity, uniform),
//   kr = ((u>>1)<<4) + ((l>>2)<<1) + p, osub = (l&3)*8, i = kr>>1.
// Coverage per token-half: 4 warps x 8 rows x 32B = full 4KB row.

__global__ void __launch_bounds__(256) monarch_embed_kernel(
    const int* __restrict__ x,
    const float* __restrict__ L,
    const float* __restrict__ R,
    float* __restrict__ out)
{
    const int tb   = blockIdx.x << 2;      // 4 tokens per CTA
    const int tid  = threadIdx.x;
    const int th   = tid >> 7;             // 0/1: token of each pair
    const int slot = tid & 127;
    const int u    = slot >> 5;            // warp within token-half
    const int l    = slot & 31;
    const int p    = u & 1;                // warp parity (uniform)
    const int kr   = ((u >> 1) << 4) + ((l >> 2) << 1) + p;   // 0..31
    const int osub = (l & 3) << 3;         // 0,8,16,24
    const int i    = kr >> 1;              // L column 0..15

    // One aligned 128-bit load covers x for all 4 tokens.
    const int4 xv = *reinterpret_cast<const int4*>(x + tb);
    const int v0 = th ? xv.y : xv.x;       // pass-0 token
    const int v1 = th ? xv.w : xv.z;       // pass-1 token

    const int k0 = v0 / 786, s0 = k0 >> 5, c0 = k0 & 31;
    const int k1 = v1 / 786, s1 = k1 >> 5, c1 = k1 & 31;
    const bool a0 = (s0 == p), a1 = (s1 == p);   // warp-uniform

    float* ob = out + (size_t)(tb + th) * 1024 + (kr << 5) + osub;
    const float z = 0.0f;

    // ---- Zero stores FIRST: no load dependency, start the store stream. ----
    if (!a0) {
        asm volatile("st.global.v8.f32 [%0], {%1,%1,%1,%1,%1,%1,%1,%1};"
            :: "l"(ob), "f"(z) : "memory");
    }
    if (!a1) {
        asm volatile("st.global.v8.f32 [%0], {%1,%1,%1,%1,%1,%1,%1,%1};"
            :: "l"(ob + 2048), "f"(z) : "memory");
    }

    // ---- Active tokens: L gather + R v8 + mul + store. ----
    float lva = 0.0f, lvb = 0.0f;
    if (a0) lva = __ldg(&L[(size_t)v0 * 16 + i]);
    if (a1) lvb = __ldg(&L[(size_t)v1 * 16 + i]);

    if (a0) {
        const float* rp = &R[((size_t)((kr << 5) + c0) << 5) + osub];
        float q0,q1,q2,q3,q4,q5,q6,q7;
        asm("ld.global.v8.f32 {%0,%1,%2,%3,%4,%5,%6,%7}, [%8];"
            : "=f"(q0), "=f"(q1), "=f"(q2), "=f"(q3),
              "=f"(q4), "=f"(q5), "=f"(q6), "=f"(q7) : "l"(rp));
        q0*=lva; q1*=lva; q2*=lva; q3*=lva;
        q4*=lva; q5*=lva; q6*=lva; q7*=lva;
        asm volatile("st.global.v8.f32 [%0], {%1,%2,%3,%4,%5,%6,%7,%8};"
            :: "l"(ob),
               "f"(q0), "f"(q1), "f"(q2), "f"(q3),
               "f"(q4), "f"(q5), "f"(q6), "f"(q7) : "memory");
    }
    if (a1) {
        const float* rp = &R[((size_t)((kr << 5) + c1) << 5) + osub];
        float w0,w1,w2,w3,w4,w5,w6,w7;
        asm("ld.global.v8.f32 {%0,%1,%2,%3,%4,%5,%6,%7}, [%8];"
            : "=f"(w0), "=f"(w1), "=f"(w2), "=f"(w3),
              "=f"(w4), "=f"(w5), "=f"(w6), "=f"(w7) : "l"(rp));
        w0*=lvb; w1*=lvb; w2*=lvb; w3*=lvb;
        w4*=lvb; w5*=lvb; w6*=lvb; w7*=lvb;
        asm volatile("st.global.v8.f32 [%0], {%1,%2,%3,%4,%5,%6,%7,%8};"
            :: "l"(ob + 2048),
               "f"(w0), "f"(w1), "f"(w2), "f"(w3),
               "f"(w4), "f"(w5), "f"(w6), "f"(w7) : "memory");
    }
}

extern "C" void kernel_launch(void* const* d_in, const int* in_sizes, int n_in,
                              void* d_out, int out_size) {
    const int*   x = (const int*)  d_in[0];   // (8, 2048) int32
    const float* L = (const float*)d_in[1];   // (64, 786, 16) f32
    const float* R = (const float*)d_in[2];   // (32, 32, 32) f32
    // d_in[3] = p : analytically folded (perfect_shuffle(64, 1024))

    const int ntok = out_size / 1024;         // 16384 tokens
    monarch_embed_kernel<<<ntok / 4, 256>>>(x, L, R, (float*)d_out);
}